// round 11
// baseline (speedup 1.0000x reference)
#include <cuda_runtime.h>
#include <cuda_bf16.h>

typedef unsigned short u16;
typedef unsigned int   u32;

#define SEQ   2048
#define HIDN  2048
#define NH    16
#define HD    128
#define NBLK  32
#define BLK   64
#define KSEL  8
#define SSTR  40
#define VPAD  144
#define SCP   65

#define STAGE_B 40960
#define GEMM_SMEM (2 * STAGE_B)

__device__ float    g_q[SEQ * HIDN];
__device__ float    g_k[SEQ * HIDN];
__device__ float    g_v[SEQ * HIDN];
__device__ float    g_kg[NBLK * HIDN];
__device__ unsigned g_sel[NH * SEQ];
__device__ float    g_o[SEQ * HIDN];
__device__ u16 g_hsHi[SEQ * HIDN];
__device__ u16 g_hsLo[SEQ * HIDN];
__device__ u16 g_WTHi[4][HIDN * HIDN];
__device__ u16 g_WTLo[4][HIDN * HIDN];
__device__ u16 g_oHi[SEQ * HIDN];
__device__ u16 g_oLo[SEQ * HIDN];

__device__ __forceinline__ float finf() { return __int_as_float(0x7f800000); }

__device__ __forceinline__ u32 cvta_s(const void* p) {
    u32 a;
    asm("{ .reg .u64 t; cvta.to.shared.u64 t, %1; cvt.u32.u64 %0, t; }" : "=r"(a) : "l"(p));
    return a;
}
__device__ __forceinline__ void cpa16(u32 dst, const void* src) {
    asm volatile("cp.async.cg.shared.global [%0], [%1], 16;" :: "r"(dst), "l"(src));
}
__device__ __forceinline__ void cpa_commit() { asm volatile("cp.async.commit_group;" ::: "memory"); }
__device__ __forceinline__ void cpa_wait1()  { asm volatile("cp.async.wait_group 1;" ::: "memory"); }
__device__ __forceinline__ void cpa_wait0()  { asm volatile("cp.async.wait_group 0;" ::: "memory"); }

__device__ __forceinline__ void ldsm4(u32* r, u32 addr) {
    asm volatile("ldmatrix.sync.aligned.m8n8.x4.shared.b16 {%0,%1,%2,%3}, [%4];"
                 : "=r"(r[0]), "=r"(r[1]), "=r"(r[2]), "=r"(r[3]) : "r"(addr));
}

__device__ __forceinline__ void mma16816(float* d, const u32* a, const u32* b) {
    asm volatile("mma.sync.aligned.m16n8k16.row.col.f32.bf16.bf16.f32 "
                 "{%0,%1,%2,%3},{%4,%5,%6,%7},{%8,%9},{%0,%1,%2,%3};"
                 : "+f"(d[0]), "+f"(d[1]), "+f"(d[2]), "+f"(d[3])
                 : "r"(a[0]), "r"(a[1]), "r"(a[2]), "r"(a[3]), "r"(b[0]), "r"(b[1]));
}

__device__ __forceinline__ void split4(const float* __restrict__ src, size_t i,
                                       u16* __restrict__ hi, u16* __restrict__ lo) {
    float4 v = *(const float4*)(src + i);
    float f[4] = {v.x, v.y, v.z, v.w};
    u16 hh[4], ll[4];
#pragma unroll
    for (int j = 0; j < 4; j++) {
        __nv_bfloat16 b = __float2bfloat16(f[j]);
        hh[j] = __bfloat16_as_ushort(b);
        ll[j] = __bfloat16_as_ushort(__float2bfloat16(f[j] - __bfloat162float(b)));
    }
    ushort4 h = {hh[0], hh[1], hh[2], hh[3]}, l = {ll[0], ll[1], ll[2], ll[3]};
    *(ushort4*)(hi + i) = h;
    *(ushort4*)(lo + i) = l;
}

__global__ __launch_bounds__(256) void split_hs_kernel(const float* __restrict__ in) {
    size_t i = ((size_t)blockIdx.x * 256 + threadIdx.x) * 4;
    split4(in, i, g_hsHi, g_hsLo);
}
__global__ __launch_bounds__(256) void split_o_kernel() {
    size_t i = ((size_t)blockIdx.x * 256 + threadIdx.x) * 4;
    split4(g_o, i, g_oHi, g_oLo);
}

__global__ __launch_bounds__(256) void splitT_kernel(const float* __restrict__ W0,
                                                     const float* __restrict__ W1,
                                                     const float* __restrict__ W2,
                                                     const float* __restrict__ W3) {
    const float* W = (blockIdx.z == 0) ? W0 : (blockIdx.z == 1) ? W1 : (blockIdx.z == 2) ? W2 : W3;
    u16* oh = g_WTHi[blockIdx.z];
    u16* ol = g_WTLo[blockIdx.z];
    __shared__ float t[32][33];
    const int tx = threadIdx.x & 31, ty = threadIdx.x >> 5;
    const int n0 = blockIdx.x * 32, k0 = blockIdx.y * 32;
    for (int r = ty; r < 32; r += 8)
        t[r][tx] = W[(size_t)(k0 + r) * HIDN + n0 + tx];
    __syncthreads();
    for (int r = ty; r < 32; r += 8) {
        float v = t[tx][r];
        __nv_bfloat16 h = __float2bfloat16(v);
        __nv_bfloat16 l = __float2bfloat16(v - __bfloat162float(h));
        size_t o = (size_t)(n0 + r) * HIDN + k0 + tx;
        oh[o] = __bfloat16_as_ushort(h);
        ol[o] = __bfloat16_as_ushort(l);
    }
}

// ============================================================
// bf16-split GEMM: cp.async 2-stage + ldmatrix fragments.
// Buffer byte offsets within a stage: Ah=0, Al=10240, Bh=20480, Bl=30720.
// ============================================================
__device__ __forceinline__ void mma_gemm_body(const u16* __restrict__ Ah,
                                              const u16* __restrict__ Al,
                                              const u16* __restrict__ Bh,
                                              const u16* __restrict__ Bl,
                                              float* __restrict__ C) {
    extern __shared__ u16 dynsm[];

    const int tid = threadIdx.x, lane = tid & 31, warp = tid >> 5;
    const int wm = (warp & 3) * 32, wn = (warp >> 2) * 64;
    const int cRow = blockIdx.y << 7, cCol = blockIdx.x << 7;
    const int lrow = tid >> 1, lhalf = (tid & 1) << 4;

    const u32 sbase = cvta_s(dynsm);
    const u32 so = (u32)(lrow * SSTR + lhalf) * 2;

    auto issue = [&](int kt, int st) {
        const size_t ga = (size_t)(cRow + lrow) * HIDN + (kt << 5) + lhalf;
        const size_t gb = (size_t)(cCol + lrow) * HIDN + (kt << 5) + lhalf;
        const u32 s0 = sbase + st * STAGE_B + so;
        cpa16(s0,         Ah + ga); cpa16(s0 + 16,         Ah + ga + 8);
        cpa16(s0 + 10240, Al + ga); cpa16(s0 + 10240 + 16, Al + ga + 8);
        cpa16(s0 + 20480, Bh + gb); cpa16(s0 + 20480 + 16, Bh + gb + 8);
        cpa16(s0 + 30720, Bl + gb); cpa16(s0 + 30720 + 16, Bl + gb + 8);
        cpa_commit();
    };

    float acc[2][8][4];
#pragma unroll
    for (int mt = 0; mt < 2; mt++)
#pragma unroll
        for (int nt = 0; nt < 8; nt++)
#pragma unroll
            for (int j = 0; j < 4; j++) acc[mt][nt][j] = 0.f;

    // ldmatrix per-lane offset (bytes): row = lane&15, kchunk = (lane>>4)*8
    const u32 lmoff = (u32)(((lane & 15) * SSTR + ((lane >> 4) << 3)) * 2);

    issue(0, 0);

    for (int kt = 0; kt < 64; kt++) {
        if (kt + 1 < 64) { issue(kt + 1, (kt + 1) & 1); cpa_wait1(); }
        else             { cpa_wait0(); }
        __syncthreads();

        const u32 stb = sbase + (u32)(kt & 1) * STAGE_B;

#pragma unroll
        for (int kk = 0; kk < 32; kk += 16) {
            u32 ah[2][4], al[2][4];
#pragma unroll
            for (int mt = 0; mt < 2; mt++) {
                const u32 arow = (u32)((wm + mt * 16) * SSTR + kk) * 2;   // bytes
                ldsm4(ah[mt], stb + arow + lmoff);
                ldsm4(al[mt], stb + 10240 + arow + lmoff);
            }
#pragma unroll
            for (int half = 0; half < 2; half++) {
                u32 bhr[2][4], blr[2][4];
#pragma unroll
                for (int nb = 0; nb < 2; nb++) {
                    const u32 brow = (u32)((wn + (half * 2 + nb) * 16) * SSTR + kk) * 2;  // bytes
                    ldsm4(bhr[nb], stb + 20480 + brow + lmoff);
                    ldsm4(blr[nb], stb + 30720 + brow + lmoff);
                }
                u32 bhf[4][2], blf[4][2];
#pragma unroll
                for (int p = 0; p < 4; p++) {
                    bhf[p][0] = bhr[p >> 1][p & 1];
                    bhf[p][1] = bhr[p >> 1][2 + (p & 1)];
                    blf[p][0] = blr[p >> 1][p & 1];
                    blf[p][1] = blr[p >> 1][2 + (p & 1)];
                }
#pragma unroll
                for (int p = 0; p < 4; p++) {
                    mma16816(acc[0][half * 4 + p], ah[0], bhf[p]);
                    mma16816(acc[1][half * 4 + p], ah[1], bhf[p]);
                }
#pragma unroll
                for (int p = 0; p < 4; p++) {
                    mma16816(acc[0][half * 4 + p], al[0], bhf[p]);
                    mma16816(acc[1][half * 4 + p], al[1], bhf[p]);
                }
#pragma unroll
                for (int p = 0; p < 4; p++) {
                    mma16816(acc[0][half * 4 + p], ah[0], blf[p]);
                    mma16816(acc[1][half * 4 + p], ah[1], blf[p]);
                }
            }
        }
        __syncthreads();
    }

    const int qrow = lane >> 2, qcol = (lane & 3) << 1;
#pragma unroll
    for (int mt = 0; mt < 2; mt++)
#pragma unroll
        for (int nt = 0; nt < 8; nt++) {
            const int r0 = cRow + wm + mt * 16 + qrow;
            const int c0 = cCol + wn + nt * 8 + qcol;
            float2 lo = {acc[mt][nt][0], acc[mt][nt][1]};
            float2 hi = {acc[mt][nt][2], acc[mt][nt][3]};
            *(float2*)(C + (size_t)r0 * HIDN + c0) = lo;
            *(float2*)(C + (size_t)(r0 + 8) * HIDN + c0) = hi;
        }
}

__global__ __launch_bounds__(256) void gemm_qkv_kernel() {
    float* C = (blockIdx.z == 0) ? g_q : (blockIdx.z == 1) ? g_k : g_v;
    mma_gemm_body(g_hsHi, g_hsLo, g_WTHi[blockIdx.z], g_WTLo[blockIdx.z], C);
}
__global__ __launch_bounds__(256) void gemm_out_kernel(float* __restrict__ out) {
    mma_gemm_body(g_oHi, g_oLo, g_WTHi[3], g_WTLo[3], out);
}

// ---- kg mean ----
__global__ void kgmean_kernel() {
    const int n = blockIdx.x;
    const int c = blockIdx.y * 256 + threadIdx.x;
    float sum = 0.f;
#pragma unroll
    for (int t = 0; t < BLK; t++) sum += g_k[(size_t)(n * BLK + t) * HIDN + c];
    g_kg[n * HIDN + c] = sum * (1.0f / 64.0f);
}

// ---- gate + top-8 ----
__global__ __launch_bounds__(256) void gate_topk_kernel() {
    __shared__ float kgs[NBLK * 129];
    const int h = blockIdx.y, s0 = blockIdx.x * 32, tid = threadIdx.x;
    for (int i = tid; i < NBLK * HD; i += 256) {
        int n = i >> 7, d = i & 127;
        kgs[n * 129 + d] = g_kg[n * HIDN + h * HD + d];
    }
    __syncthreads();
    const int warp = tid >> 5, lane = tid & 31;
    for (int r = 0; r < 4; r++) {
        const int s = s0 + warp * 4 + r;
        const float* qrow = g_q + (size_t)s * HIDN + h * HD;
        float g = 0.f;
#pragma unroll 8
        for (int d = 0; d < HD; d++) g += __ldg(qrow + d) * kgs[lane * 129 + d];
        const int qb = s >> 6;
        if (lane == qb) g = finf();
        else if (lane > qb) g = -finf();
        unsigned mask = 0;
        float work = g;
#pragma unroll
        for (int it = 0; it < KSEL; it++) {
            float v = work; int idx = lane;
#pragma unroll
            for (int off = 16; off; off >>= 1) {
                float ov = __shfl_xor_sync(0xffffffffu, v, off);
                int   oi = __shfl_xor_sync(0xffffffffu, idx, off);
                if (ov > v || (ov == v && oi < idx)) { v = ov; idx = oi; }
            }
            if (v > -finf()) mask |= (1u << idx);
            if (lane == idx) work = -finf();
        }
        if (lane == 0) g_sel[h * SEQ + s] = mask;
    }
}

// ---- query-block-tiled block-sparse attention ----
__global__ __launch_bounds__(256, 2) void attn2_kernel() {
    extern __shared__ float dyn[];
    float* kb = dyn;
    float* vb = dyn + 64 * VPAD;
    float* sc = dyn + 128 * VPAD;
    __shared__ unsigned selm[64];
    __shared__ unsigned s_uni;

    const int qb = blockIdx.x, h = blockIdx.y;
    const int tid = threadIdx.x, qi = tid >> 2, j = tid & 3;
    const int s = qb * BLK + qi;
    const unsigned qmask = 0xFu << ((tid & 31) & ~3);
    const float sm_scale = 0.08838834764831845f;

    if (tid < 64) selm[tid] = g_sel[h * SEQ + qb * BLK + tid];
    __syncthreads();
    if (tid == 0) {
        unsigned u = 0;
#pragma unroll
        for (int i = 0; i < 64; i++) u |= selm[i];
        s_uni = u;
    }

    float qreg[32];
    {
        const float4* qp = (const float4*)(g_q + (size_t)s * HIDN + h * HD + j * 32);
#pragma unroll
        for (int i = 0; i < 8; i++) {
            float4 t4 = qp[i];
            qreg[4 * i] = t4.x; qreg[4 * i + 1] = t4.y;
            qreg[4 * i + 2] = t4.z; qreg[4 * i + 3] = t4.w;
        }
    }
    __syncthreads();
    unsigned uni = s_uni;
    const unsigned mysel = selm[qi];

    float m = -finf(), l = 0.f, acc[32];
#pragma unroll
    for (int i = 0; i < 32; i++) acc[i] = 0.f;

    while (uni) {
        const int n = __ffs(uni) - 1;
        uni &= uni - 1;

        for (int x = tid; x < 2048; x += 256) {
            const int r = x >> 5, d = (x & 31) << 2;
            const size_t g = (size_t)(n * BLK + r) * HIDN + h * HD + d;
            const int dst = r * VPAD + (d >> 5) * 36 + (d & 31);
            *(float4*)(kb + dst) = *(const float4*)(g_k + g);
            *(float4*)(vb + dst) = *(const float4*)(g_v + g);
        }
        __syncthreads();

        if ((mysel >> n) & 1) {
            float smax = -finf();
            const int kcaus = (n == qb) ? qi : 63;
            for (int k = 0; k < 64; k++) {
                const float* kp = kb + k * VPAD + j * 36;
                float p0 = 0.f, p1 = 0.f, p2 = 0.f, p3 = 0.f;
#pragma unroll
                for (int i = 0; i < 32; i += 4) {
                    p0 += qreg[i] * kp[i];
                    p1 += qreg[i + 1] * kp[i + 1];
                    p2 += qreg[i + 2] * kp[i + 2];
                    p3 += qreg[i + 3] * kp[i + 3];
                }
                float p = (p0 + p1) + (p2 + p3);
                p += __shfl_xor_sync(qmask, p, 1);
                p += __shfl_xor_sync(qmask, p, 2);
                const float scv = (k <= kcaus) ? p * sm_scale : -finf();
                if ((k & 3) == j) sc[qi * SCP + k] = scv;
                smax = fmaxf(smax, scv);
            }
            __syncwarp(qmask);

            const float newm = fmaxf(m, smax);
            const float alpha = __expf(m - newm);
            m = newm;
            l *= alpha;
#pragma unroll
            for (int i = 0; i < 32; i++) acc[i] *= alpha;

            float lsum = 0.f;
#pragma unroll
            for (int kk = 0; kk < 16; kk++) {
                const int k = (kk << 2) | j;
                const float p = __expf(sc[qi * SCP + k] - m);
                sc[qi * SCP + k] = p;
                lsum += p;
            }
            lsum += __shfl_xor_sync(qmask, lsum, 1);
            lsum += __shfl_xor_sync(qmask, lsum, 2);
            l += lsum;
            __syncwarp(qmask);

            for (int k = 0; k < 64; k++) {
                const float p = sc[qi * SCP + k];
                const float* vp = vb + k * VPAD + j * 36;
#pragma unroll
                for (int i = 0; i < 32; i++) acc[i] += p * vp[i];
            }
        }
        __syncthreads();
    }

    const float inv = 1.f / l;
    float4* op = (float4*)(g_o + (size_t)s * HIDN + h * HD + j * 32);
#pragma unroll
    for (int i = 0; i < 8; i++) {
        float4 t4 = {acc[4 * i] * inv, acc[4 * i + 1] * inv,
                     acc[4 * i + 2] * inv, acc[4 * i + 3] * inv};
        op[i] = t4;
    }
}

#define ATTN_SMEM ((128 * VPAD + 64 * SCP) * 4)

extern "C" void kernel_launch(void* const* d_in, const int* in_sizes, int n_in,
                              void* d_out, int out_size) {
    const float* hs = (const float*)d_in[0];
    const float* Wq = (const float*)d_in[1];
    const float* Wk = (const float*)d_in[2];
    const float* Wv = (const float*)d_in[3];
    const float* Wo = (const float*)d_in[4];
    float* out = (float*)d_out;

    cudaFuncSetAttribute(attn2_kernel, cudaFuncAttributeMaxDynamicSharedMemorySize, ATTN_SMEM);
    cudaFuncSetAttribute(gemm_qkv_kernel, cudaFuncAttributeMaxDynamicSharedMemorySize, GEMM_SMEM);
    cudaFuncSetAttribute(gemm_out_kernel, cudaFuncAttributeMaxDynamicSharedMemorySize, GEMM_SMEM);

    split_hs_kernel<<<SEQ * HIDN / 1024, 256>>>(hs);
    dim3 gw(HIDN / 32, HIDN / 32, 4);
    splitT_kernel<<<gw, 256>>>(Wq, Wk, Wv, Wo);

    dim3 gq(HIDN / 128, SEQ / 128, 3);
    gemm_qkv_kernel<<<gq, 256, GEMM_SMEM>>>();

    dim3 gk(NBLK, HIDN / 256);
    kgmean_kernel<<<gk, 256>>>();
    dim3 gg(SEQ / 32, NH);
    gate_topk_kernel<<<gg, 256>>>();

    dim3 ga(NBLK, NH);
    attn2_kernel<<<ga, 256, ATTN_SMEM>>>();

    split_o_kernel<<<SEQ * HIDN / 1024, 256>>>();
    dim3 go(HIDN / 128, SEQ / 128);
    gemm_out_kernel<<<go, 256, GEMM_SMEM>>>(out);
}

// round 15
// speedup vs baseline: 1.8500x; 1.8500x over previous
#include <cuda_runtime.h>
#include <cuda_bf16.h>

typedef unsigned short u16;
typedef unsigned int   u32;

#define SEQ   2048
#define HIDN  2048
#define NH    16
#define HD    128
#define NBLK  32
#define BLK   64
#define KSEL  8
#define SSTR  40

#define STAGE_B 40960
#define GEMM_SMEM (2 * STAGE_B)

// attn3 smem byte offsets (all strides ≡16 mod 128 -> conflict-free ldmatrix)
#define OFF_QHI  0         // 64 x 136 u16
#define OFF_QLO  17408
#define OFF_KHI  34816
#define OFF_KLO  52224
#define OFF_VTHI 69632     // 128 x 72 u16
#define OFF_VTLO 88064
#define OFF_S    106496    // 64 x 65 f32
#define OFF_PHI  123136    // 64 x 72 u16
#define OFF_PLO  132352
#define OFF_STATE 141568   // m[64], l[64], alpha[64] f32 + selm[64] u32
#define ATTN3_SMEM (141568 + 64 * 16)

__device__ float    g_q[SEQ * HIDN];
__device__ float    g_k[SEQ * HIDN];
__device__ float    g_v[SEQ * HIDN];
__device__ float    g_kg[NBLK * HIDN];
__device__ unsigned g_sel[NH * SEQ];
__device__ float    g_o[SEQ * HIDN];
__device__ u16 g_hsHi[SEQ * HIDN];
__device__ u16 g_hsLo[SEQ * HIDN];
__device__ u16 g_WTHi[4][HIDN * HIDN];
__device__ u16 g_WTLo[4][HIDN * HIDN];
__device__ u16 g_oHi[SEQ * HIDN];
__device__ u16 g_oLo[SEQ * HIDN];
__device__ u16 g_qHi[SEQ * HIDN];
__device__ u16 g_qLo[SEQ * HIDN];
__device__ u16 g_kHi[SEQ * HIDN];
__device__ u16 g_kLo[SEQ * HIDN];
__device__ u16 g_vtHi[SEQ * HIDN];   // per head: [128 d][2048 s]
__device__ u16 g_vtLo[SEQ * HIDN];

__device__ __forceinline__ float finf() { return __int_as_float(0x7f800000); }

__device__ __forceinline__ u32 cvta_s(const void* p) {
    u32 a;
    asm("{ .reg .u64 t; cvta.to.shared.u64 t, %1; cvt.u32.u64 %0, t; }" : "=r"(a) : "l"(p));
    return a;
}
__device__ __forceinline__ void cpa16(u32 dst, const void* src) {
    asm volatile("cp.async.cg.shared.global [%0], [%1], 16;" :: "r"(dst), "l"(src));
}
__device__ __forceinline__ void cpa_commit() { asm volatile("cp.async.commit_group;" ::: "memory"); }
__device__ __forceinline__ void cpa_wait1()  { asm volatile("cp.async.wait_group 1;" ::: "memory"); }
__device__ __forceinline__ void cpa_wait0()  { asm volatile("cp.async.wait_group 0;" ::: "memory"); }

__device__ __forceinline__ void ldsm4(u32* r, u32 addr) {
    asm volatile("ldmatrix.sync.aligned.m8n8.x4.shared.b16 {%0,%1,%2,%3}, [%4];"
                 : "=r"(r[0]), "=r"(r[1]), "=r"(r[2]), "=r"(r[3]) : "r"(addr));
}
__device__ __forceinline__ void mma16816(float* d, const u32* a, const u32* b) {
    asm volatile("mma.sync.aligned.m16n8k16.row.col.f32.bf16.bf16.f32 "
                 "{%0,%1,%2,%3},{%4,%5,%6,%7},{%8,%9},{%0,%1,%2,%3};"
                 : "+f"(d[0]), "+f"(d[1]), "+f"(d[2]), "+f"(d[3])
                 : "r"(a[0]), "r"(a[1]), "r"(a[2]), "r"(a[3]), "r"(b[0]), "r"(b[1]));
}

__device__ __forceinline__ void split4(const float* __restrict__ src, size_t i,
                                       u16* __restrict__ hi, u16* __restrict__ lo) {
    float4 v = *(const float4*)(src + i);
    float f[4] = {v.x, v.y, v.z, v.w};
    u16 hh[4], ll[4];
#pragma unroll
    for (int j = 0; j < 4; j++) {
        __nv_bfloat16 b = __float2bfloat16(f[j]);
        hh[j] = __bfloat16_as_ushort(b);
        ll[j] = __bfloat16_as_ushort(__float2bfloat16(f[j] - __bfloat162float(b)));
    }
    ushort4 h = {hh[0], hh[1], hh[2], hh[3]}, l = {ll[0], ll[1], ll[2], ll[3]};
    *(ushort4*)(hi + i) = h;
    *(ushort4*)(lo + i) = l;
}

__global__ __launch_bounds__(256) void split_hs_kernel(const float* __restrict__ in) {
    size_t i = ((size_t)blockIdx.x * 256 + threadIdx.x) * 4;
    split4(in, i, g_hsHi, g_hsLo);
}
__global__ __launch_bounds__(256) void split_o_kernel() {
    size_t i = ((size_t)blockIdx.x * 256 + threadIdx.x) * 4;
    split4(g_o, i, g_oHi, g_oLo);
}
__global__ __launch_bounds__(256) void split_q_kernel() {
    size_t i = ((size_t)blockIdx.x * 256 + threadIdx.x) * 4;
    split4(g_q, i, g_qHi, g_qLo);
}
__global__ __launch_bounds__(256) void split_k_kernel() {
    size_t i = ((size_t)blockIdx.x * 256 + threadIdx.x) * 4;
    split4(g_k, i, g_kHi, g_kLo);
}

__global__ __launch_bounds__(256) void splitT_kernel(const float* __restrict__ W0,
                                                     const float* __restrict__ W1,
                                                     const float* __restrict__ W2,
                                                     const float* __restrict__ W3) {
    const float* W = (blockIdx.z == 0) ? W0 : (blockIdx.z == 1) ? W1 : (blockIdx.z == 2) ? W2 : W3;
    u16* oh = g_WTHi[blockIdx.z];
    u16* ol = g_WTLo[blockIdx.z];
    __shared__ float t[32][33];
    const int tx = threadIdx.x & 31, ty = threadIdx.x >> 5;
    const int n0 = blockIdx.x * 32, k0 = blockIdx.y * 32;
    for (int r = ty; r < 32; r += 8)
        t[r][tx] = W[(size_t)(k0 + r) * HIDN + n0 + tx];
    __syncthreads();
    for (int r = ty; r < 32; r += 8) {
        float v = t[tx][r];
        __nv_bfloat16 h = __float2bfloat16(v);
        __nv_bfloat16 l = __float2bfloat16(v - __bfloat162float(h));
        size_t o = (size_t)(n0 + r) * HIDN + k0 + tx;
        oh[o] = __bfloat16_as_ushort(h);
        ol[o] = __bfloat16_as_ushort(l);
    }
}

// ---- V transpose+split per head: vt[h*128+d][s] ----
__global__ __launch_bounds__(256) void vtsplit_kernel() {
    __shared__ float t[32][33];
    const int tx = threadIdx.x & 31, ty = threadIdx.x >> 5;
    const int s0 = blockIdx.x * 32, d0 = blockIdx.y * 32, h = blockIdx.z;
    for (int r = ty; r < 32; r += 8)
        t[r][tx] = g_v[(size_t)(s0 + r) * HIDN + h * HD + d0 + tx];
    __syncthreads();
    for (int r = ty; r < 32; r += 8) {
        float v = t[tx][r];   // = v[s0+tx][d0+r]
        __nv_bfloat16 hh = __float2bfloat16(v);
        __nv_bfloat16 ll = __float2bfloat16(v - __bfloat162float(hh));
        size_t o = (size_t)(h * HD + d0 + r) * SEQ + s0 + tx;
        g_vtHi[o] = __bfloat16_as_ushort(hh);
        g_vtLo[o] = __bfloat16_as_ushort(ll);
    }
}

// ---- bf16-split GEMM (unchanged, passing) ----
__device__ __forceinline__ void mma_gemm_body(const u16* __restrict__ Ah,
                                              const u16* __restrict__ Al,
                                              const u16* __restrict__ Bh,
                                              const u16* __restrict__ Bl,
                                              float* __restrict__ C) {
    extern __shared__ u16 dynsm[];
    const int tid = threadIdx.x, lane = tid & 31, warp = tid >> 5;
    const int wm = (warp & 3) * 32, wn = (warp >> 2) * 64;
    const int cRow = blockIdx.y << 7, cCol = blockIdx.x << 7;
    const int lrow = tid >> 1, lhalf = (tid & 1) << 4;
    const u32 sbase = cvta_s(dynsm);
    const u32 so = (u32)(lrow * SSTR + lhalf) * 2;

    auto issue = [&](int kt, int st) {
        const size_t ga = (size_t)(cRow + lrow) * HIDN + (kt << 5) + lhalf;
        const size_t gb = (size_t)(cCol + lrow) * HIDN + (kt << 5) + lhalf;
        const u32 s0 = sbase + st * STAGE_B + so;
        cpa16(s0,         Ah + ga); cpa16(s0 + 16,         Ah + ga + 8);
        cpa16(s0 + 10240, Al + ga); cpa16(s0 + 10240 + 16, Al + ga + 8);
        cpa16(s0 + 20480, Bh + gb); cpa16(s0 + 20480 + 16, Bh + gb + 8);
        cpa16(s0 + 30720, Bl + gb); cpa16(s0 + 30720 + 16, Bl + gb + 8);
        cpa_commit();
    };

    float acc[2][8][4];
#pragma unroll
    for (int mt = 0; mt < 2; mt++)
#pragma unroll
        for (int nt = 0; nt < 8; nt++)
#pragma unroll
            for (int j = 0; j < 4; j++) acc[mt][nt][j] = 0.f;

    const u32 lmoff = (u32)(((lane & 15) * SSTR + ((lane >> 4) << 3)) * 2);
    issue(0, 0);

    for (int kt = 0; kt < 64; kt++) {
        if (kt + 1 < 64) { issue(kt + 1, (kt + 1) & 1); cpa_wait1(); }
        else             { cpa_wait0(); }
        __syncthreads();
        const u32 stb = sbase + (u32)(kt & 1) * STAGE_B;
#pragma unroll
        for (int kk = 0; kk < 32; kk += 16) {
            u32 ah[2][4], al[2][4];
#pragma unroll
            for (int mt = 0; mt < 2; mt++) {
                const u32 arow = (u32)((wm + mt * 16) * SSTR + kk) * 2;
                ldsm4(ah[mt], stb + arow + lmoff);
                ldsm4(al[mt], stb + 10240 + arow + lmoff);
            }
#pragma unroll
            for (int half = 0; half < 2; half++) {
                u32 bhr[2][4], blr[2][4];
#pragma unroll
                for (int nb = 0; nb < 2; nb++) {
                    const u32 brow = (u32)((wn + (half * 2 + nb) * 16) * SSTR + kk) * 2;
                    ldsm4(bhr[nb], stb + 20480 + brow + lmoff);
                    ldsm4(blr[nb], stb + 30720 + brow + lmoff);
                }
                u32 bhf[4][2], blf[4][2];
#pragma unroll
                for (int p = 0; p < 4; p++) {
                    bhf[p][0] = bhr[p >> 1][p & 1];
                    bhf[p][1] = bhr[p >> 1][2 + (p & 1)];
                    blf[p][0] = blr[p >> 1][p & 1];
                    blf[p][1] = blr[p >> 1][2 + (p & 1)];
                }
#pragma unroll
                for (int p = 0; p < 4; p++) {
                    mma16816(acc[0][half * 4 + p], ah[0], bhf[p]);
                    mma16816(acc[1][half * 4 + p], ah[1], bhf[p]);
                }
#pragma unroll
                for (int p = 0; p < 4; p++) {
                    mma16816(acc[0][half * 4 + p], al[0], bhf[p]);
                    mma16816(acc[1][half * 4 + p], al[1], bhf[p]);
                }
#pragma unroll
                for (int p = 0; p < 4; p++) {
                    mma16816(acc[0][half * 4 + p], ah[0], blf[p]);
                    mma16816(acc[1][half * 4 + p], ah[1], blf[p]);
                }
            }
        }
        __syncthreads();
    }

    const int qrow = lane >> 2, qcol = (lane & 3) << 1;
#pragma unroll
    for (int mt = 0; mt < 2; mt++)
#pragma unroll
        for (int nt = 0; nt < 8; nt++) {
            const int r0 = cRow + wm + mt * 16 + qrow;
            const int c0 = cCol + wn + nt * 8 + qcol;
            float2 lo = {acc[mt][nt][0], acc[mt][nt][1]};
            float2 hi = {acc[mt][nt][2], acc[mt][nt][3]};
            *(float2*)(C + (size_t)r0 * HIDN + c0) = lo;
            *(float2*)(C + (size_t)(r0 + 8) * HIDN + c0) = hi;
        }
}

__global__ __launch_bounds__(256) void gemm_qkv_kernel() {
    float* C = (blockIdx.z == 0) ? g_q : (blockIdx.z == 1) ? g_k : g_v;
    mma_gemm_body(g_hsHi, g_hsLo, g_WTHi[blockIdx.z], g_WTLo[blockIdx.z], C);
}
__global__ __launch_bounds__(256) void gemm_out_kernel(float* __restrict__ out) {
    mma_gemm_body(g_oHi, g_oLo, g_WTHi[3], g_WTLo[3], out);
}

__global__ void kgmean_kernel() {
    const int n = blockIdx.x;
    const int c = blockIdx.y * 256 + threadIdx.x;
    float sum = 0.f;
#pragma unroll
    for (int t = 0; t < BLK; t++) sum += g_k[(size_t)(n * BLK + t) * HIDN + c];
    g_kg[n * HIDN + c] = sum * (1.0f / 64.0f);
}

__global__ __launch_bounds__(256) void gate_topk_kernel() {
    __shared__ float kgs[NBLK * 129];
    const int h = blockIdx.y, s0 = blockIdx.x * 32, tid = threadIdx.x;
    for (int i = tid; i < NBLK * HD; i += 256) {
        int n = i >> 7, d = i & 127;
        kgs[n * 129 + d] = g_kg[n * HIDN + h * HD + d];
    }
    __syncthreads();
    const int warp = tid >> 5, lane = tid & 31;
    for (int r = 0; r < 4; r++) {
        const int s = s0 + warp * 4 + r;
        const float* qrow = g_q + (size_t)s * HIDN + h * HD;
        float g = 0.f;
#pragma unroll 8
        for (int d = 0; d < HD; d++) g += __ldg(qrow + d) * kgs[lane * 129 + d];
        const int qb = s >> 6;
        if (lane == qb) g = finf();
        else if (lane > qb) g = -finf();
        unsigned mask = 0;
        float work = g;
#pragma unroll
        for (int it = 0; it < KSEL; it++) {
            float v = work; int idx = lane;
#pragma unroll
            for (int off = 16; off; off >>= 1) {
                float ov = __shfl_xor_sync(0xffffffffu, v, off);
                int   oi = __shfl_xor_sync(0xffffffffu, idx, off);
                if (ov > v || (ov == v && oi < idx)) { v = ov; idx = oi; }
            }
            if (v > -finf()) mask |= (1u << idx);
            if (lane == idx) work = -finf();
        }
        if (lane == 0) g_sel[h * SEQ + s] = mask;
    }
}

// ============================================================
// attn3: tensor-core block-sparse attention.
// CTA=(qblock, head), 8 warps. 3-term bf16-split QK^T and PV mma.
// ============================================================
__global__ __launch_bounds__(256, 1) void attn3_kernel() {
    extern __shared__ unsigned char sm[];
    const u32 sb = cvta_s(sm);
    float* Ssm   = (float*)(sm + OFF_S);
    float* m_s   = (float*)(sm + OFF_STATE);
    float* l_s   = (float*)(sm + OFF_STATE + 256);
    float* al_s  = (float*)(sm + OFF_STATE + 512);
    unsigned* selm = (unsigned*)(sm + OFF_STATE + 768);

    const int qb = blockIdx.x, h = blockIdx.y;
    const int tid = threadIdx.x, lane = tid & 31, warp = tid >> 5;
    const float sm_scale = 0.08838834764831845f;

    if (tid < 64) {
        selm[tid] = g_sel[h * SEQ + qb * BLK + tid];
        m_s[tid] = -finf();
        l_s[tid] = 0.f;
    }

    // load Q tile (64 x 128 bf16 hi/lo) into padded smem (stride 272B)
    {
#pragma unroll
        for (int c = 0; c < 4; c++) {
            const int chunk = tid + c * 256;           // 0..1023
            const int row = chunk >> 4, c16 = chunk & 15;
            const size_t g = (size_t)(qb * BLK + row) * HIDN + h * HD + c16 * 8;
            const u32 dst = sb + (u32)(row * 272 + c16 * 16);
            cpa16(dst + OFF_QHI, g_qHi + g);
            cpa16(dst + OFF_QLO, g_qLo + g);
        }
        cpa_commit();
    }
    __syncthreads();
    unsigned uni = 0;
    if (tid == 0) { }
    // union computed by all threads cheaply:
    {
        unsigned u = 0;
#pragma unroll
        for (int i = 0; i < 64; i += 8) u |= selm[i] | selm[i+1] | selm[i+2] | selm[i+3]
                                           | selm[i+4] | selm[i+5] | selm[i+6] | selm[i+7];
        uni = u;
    }
    cpa_wait0();
    __syncthreads();

    const u32 lmoffA = (u32)((lane & 15) * 272 + ((lane >> 4) << 4));  // 272B-stride tiles
    const u32 lmoffP = (u32)((lane & 15) * 144 + ((lane >> 4) << 4));  // 144B-stride tiles
    const int qrow = lane >> 2, qcol = (lane & 3) << 1;
    const int qi = tid >> 2, jq = tid & 3;
    const unsigned qmask = 0xFu << (lane & ~3);

    // PV accumulators: warp = (mt = warp&3 rows, dh = warp>>2 dims)
    const int mt = warp & 3, nh = warp >> 2;   // score roles
    const int dh = warp >> 2;                  // pv role shares mt
    float oacc[8][4];
#pragma unroll
    for (int nt = 0; nt < 8; nt++)
#pragma unroll
        for (int j = 0; j < 4; j++) oacc[nt][j] = 0.f;

    while (uni) {
        const int n = __ffs(uni) - 1;
        uni &= uni - 1;

        // ---- load K (64x256B) and VT (128x128B) tiles ----
#pragma unroll
        for (int c = 0; c < 4; c++) {
            const int chunk = tid + c * 256;
            const int krow = chunk >> 4, kc = chunk & 15;
            const size_t gk = (size_t)(n * BLK + krow) * HIDN + h * HD + kc * 8;
            const u32 kdst = sb + (u32)(krow * 272 + kc * 16);
            cpa16(kdst + OFF_KHI, g_kHi + gk);
            cpa16(kdst + OFF_KLO, g_kLo + gk);
            const int vrow = chunk >> 3, vc = chunk & 7;
            const size_t gv = (size_t)(h * HD + vrow) * SEQ + n * BLK + vc * 8;
            const u32 vdst = sb + (u32)(vrow * 144 + vc * 16);
            cpa16(vdst + OFF_VTHI, g_vtHi + gv);
            cpa16(vdst + OFF_VTLO, g_vtLo + gv);
        }
        cpa_commit();
        cpa_wait0();
        __syncthreads();

        // ---- score mma: warp computes S[mt*16..+16][nh*32..+32] ----
        {
            float sacc[4][4];
#pragma unroll
            for (int nt = 0; nt < 4; nt++)
#pragma unroll
                for (int j = 0; j < 4; j++) sacc[nt][j] = 0.f;

#pragma unroll
            for (int kk = 0; kk < 8; kk++) {
                const u32 kkb = (u32)kk * 32;
                u32 ah[4], al[4];
                ldsm4(ah, sb + OFF_QHI + (u32)(mt * 16) * 272 + kkb + lmoffA);
                ldsm4(al, sb + OFF_QLO + (u32)(mt * 16) * 272 + kkb + lmoffA);
                u32 bhr[2][4], blr[2][4];
#pragma unroll
                for (int nb = 0; nb < 2; nb++) {
                    const u32 brow = (u32)(nh * 32 + nb * 16) * 272 + kkb;
                    ldsm4(bhr[nb], sb + OFF_KHI + brow + lmoffA);
                    ldsm4(blr[nb], sb + OFF_KLO + brow + lmoffA);
                }
                u32 bhf[4][2], blf[4][2];
#pragma unroll
                for (int p = 0; p < 4; p++) {
                    bhf[p][0] = bhr[p >> 1][p & 1];
                    bhf[p][1] = bhr[p >> 1][2 + (p & 1)];
                    blf[p][0] = blr[p >> 1][p & 1];
                    blf[p][1] = blr[p >> 1][2 + (p & 1)];
                }
#pragma unroll
                for (int p = 0; p < 4; p++) mma16816(sacc[p], ah, bhf[p]);
#pragma unroll
                for (int p = 0; p < 4; p++) mma16816(sacc[p], al, bhf[p]);
#pragma unroll
                for (int p = 0; p < 4; p++) mma16816(sacc[p], ah, blf[p]);
            }
            // store S (fp32, row stride 65)
#pragma unroll
            for (int nt = 0; nt < 4; nt++) {
                const int r0 = mt * 16 + qrow, c0 = nh * 32 + nt * 8 + qcol;
                Ssm[r0 * 65 + c0]       = sacc[nt][0];
                Ssm[r0 * 65 + c0 + 1]   = sacc[nt][1];
                Ssm[(r0 + 8) * 65 + c0]     = sacc[nt][2];
                Ssm[(r0 + 8) * 65 + c0 + 1] = sacc[nt][3];
            }
        }
        __syncthreads();

        // ---- softmax (quad per query) ----
        {
            const int sel = (selm[qi] >> n) & 1;
            u16* phi = (u16*)(sm + OFF_PHI) + qi * 72;
            u16* plo = (u16*)(sm + OFF_PLO) + qi * 72;
            if (sel) {
                const int kcaus = (n == qb) ? qi : 63;
                float sv[16];
                float mx = -finf();
#pragma unroll
                for (int t = 0; t < 16; t++) {
                    const int k = jq + 4 * t;
                    float v = (k <= kcaus) ? Ssm[qi * 65 + k] * sm_scale : -finf();
                    sv[t] = v;
                    mx = fmaxf(mx, v);
                }
                mx = fmaxf(mx, __shfl_xor_sync(qmask, mx, 1));
                mx = fmaxf(mx, __shfl_xor_sync(qmask, mx, 2));
                const float mold = m_s[qi];
                const float newm = fmaxf(mold, mx);
                const float alpha = __expf(mold - newm);
                float lsum = 0.f;
#pragma unroll
                for (int t = 0; t < 16; t++) {
                    const int k = jq + 4 * t;
                    const float p = __expf(sv[t] - newm);
                    lsum += p;
                    __nv_bfloat16 ph = __float2bfloat16(p);
                    phi[k] = __bfloat16_as_ushort(ph);
                    plo[k] = __bfloat16_as_ushort(__float2bfloat16(p - __bfloat162float(ph)));
                }
                lsum += __shfl_xor_sync(qmask, lsum, 1);
                lsum += __shfl_xor_sync(qmask, lsum, 2);
                if (jq == 0) {
                    al_s[qi] = alpha;
                    m_s[qi] = newm;
                    l_s[qi] = l_s[qi] * alpha + lsum;
                }
            } else {
#pragma unroll
                for (int t = 0; t < 16; t++) {
                    const int k = jq + 4 * t;
                    phi[k] = 0; plo[k] = 0;
                }
                if (jq == 0) al_s[qi] = 1.f;
            }
        }
        __syncthreads();

        // ---- PV mma: warp = (mt rows, dh*64 dims) ----
        {
            const float a0 = al_s[mt * 16 + qrow];
            const float a1 = al_s[mt * 16 + qrow + 8];
#pragma unroll
            for (int nt = 0; nt < 8; nt++) {
                oacc[nt][0] *= a0; oacc[nt][1] *= a0;
                oacc[nt][2] *= a1; oacc[nt][3] *= a1;
            }
#pragma unroll
            for (int ks = 0; ks < 4; ks++) {
                const u32 kkb = (u32)ks * 32;
                u32 ph[4], pl[4];
                ldsm4(ph, sb + OFF_PHI + (u32)(mt * 16) * 144 + kkb + lmoffP);
                ldsm4(pl, sb + OFF_PLO + (u32)(mt * 16) * 144 + kkb + lmoffP);
                u32 vhr[4][4], vlr[4][4];
#pragma unroll
                for (int nb = 0; nb < 4; nb++) {
                    const u32 brow = (u32)(dh * 64 + nb * 16) * 144 + kkb;
                    ldsm4(vhr[nb], sb + OFF_VTHI + brow + lmoffP);
                    ldsm4(vlr[nb], sb + OFF_VTLO + brow + lmoffP);
                }
                u32 vhf[8][2], vlf[8][2];
#pragma unroll
                for (int p = 0; p < 8; p++) {
                    vhf[p][0] = vhr[p >> 1][p & 1];
                    vhf[p][1] = vhr[p >> 1][2 + (p & 1)];
                    vlf[p][0] = vlr[p >> 1][p & 1];
                    vlf[p][1] = vlr[p >> 1][2 + (p & 1)];
                }
#pragma unroll
                for (int p = 0; p < 8; p++) mma16816(oacc[p], ph, vhf[p]);
#pragma unroll
                for (int p = 0; p < 8; p++) mma16816(oacc[p], pl, vhf[p]);
#pragma unroll
                for (int p = 0; p < 8; p++) mma16816(oacc[p], ph, vlf[p]);
            }
        }
        __syncthreads();
    }

    // epilogue
    {
        const int r0 = mt * 16 + qrow, r1 = r0 + 8;
        const float il0 = 1.f / l_s[r0], il1 = 1.f / l_s[r1];
#pragma unroll
        for (int nt = 0; nt < 8; nt++) {
            const int c0 = dh * 64 + nt * 8 + qcol;
            float2 lo = {oacc[nt][0] * il0, oacc[nt][1] * il0};
            float2 hi = {oacc[nt][2] * il1, oacc[nt][3] * il1};
            *(float2*)(g_o + (size_t)(qb * BLK + r0) * HIDN + h * HD + c0) = lo;
            *(float2*)(g_o + (size_t)(qb * BLK + r1) * HIDN + h * HD + c0) = hi;
        }
    }
}

extern "C" void kernel_launch(void* const* d_in, const int* in_sizes, int n_in,
                              void* d_out, int out_size) {
    const float* hs = (const float*)d_in[0];
    const float* Wq = (const float*)d_in[1];
    const float* Wk = (const float*)d_in[2];
    const float* Wv = (const float*)d_in[3];
    const float* Wo = (const float*)d_in[4];
    float* out = (float*)d_out;

    cudaFuncSetAttribute(attn3_kernel, cudaFuncAttributeMaxDynamicSharedMemorySize, ATTN3_SMEM);
    cudaFuncSetAttribute(gemm_qkv_kernel, cudaFuncAttributeMaxDynamicSharedMemorySize, GEMM_SMEM);
    cudaFuncSetAttribute(gemm_out_kernel, cudaFuncAttributeMaxDynamicSharedMemorySize, GEMM_SMEM);

    split_hs_kernel<<<SEQ * HIDN / 1024, 256>>>(hs);
    dim3 gw(HIDN / 32, HIDN / 32, 4);
    splitT_kernel<<<gw, 256>>>(Wq, Wk, Wv, Wo);

    dim3 gq(HIDN / 128, SEQ / 128, 3);
    gemm_qkv_kernel<<<gq, 256, GEMM_SMEM>>>();

    split_q_kernel<<<SEQ * HIDN / 1024, 256>>>();
    split_k_kernel<<<SEQ * HIDN / 1024, 256>>>();
    dim3 gv(SEQ / 32, HD / 32, NH);
    vtsplit_kernel<<<gv, 256>>>();

    dim3 gk(NBLK, HIDN / 256);
    kgmean_kernel<<<gk, 256>>>();
    dim3 gg(SEQ / 32, NH);
    gate_topk_kernel<<<gg, 256>>>();

    dim3 ga(NBLK, NH);
    attn3_kernel<<<ga, 256, ATTN3_SMEM>>>();

    split_o_kernel<<<SEQ * HIDN / 1024, 256>>>();
    dim3 go(HIDN / 128, SEQ / 128);
    gemm_out_kernel<<<go, 256, GEMM_SMEM>>>(out);
}